// round 2
// baseline (speedup 1.0000x reference)
#include <cuda_runtime.h>
#include <math.h>

#define BB 8
#define NN 1024
#define DM 512
#define NH 8
#define HD 64
#define NS_TOK 1

typedef unsigned long long ull;

// Scratch (device globals: no allocations allowed in kernel_launch)
__device__ float g_qkv[(size_t)BB * NN * 3 * DM];   // [b][n][1536] : q|k|v
__device__ float g_attn[(size_t)BB * NN * DM];      // [b][n][512]

// ---------------------------------------------------------------------------
// Packed f32x2 helpers (sm_100+): one SASS op per 2 fp32 lanes.
// ---------------------------------------------------------------------------
__device__ __forceinline__ ull ffma2(ull a, ull b, ull c) {
    ull d;
    asm("fma.rn.f32x2 %0, %1, %2, %3;" : "=l"(d) : "l"(a), "l"(b), "l"(c));
    return d;
}
__device__ __forceinline__ ull fadd2(ull a, ull b) {
    ull d;
    asm("add.rn.f32x2 %0, %1, %2;" : "=l"(d) : "l"(a), "l"(b));
    return d;
}
__device__ __forceinline__ ull fmul2(ull a, ull b) {
    ull d;
    asm("mul.rn.f32x2 %0, %1, %2;" : "=l"(d) : "l"(a), "l"(b));
    return d;
}
__device__ __forceinline__ ull pack2(float x, float y) {
    ull d;
    asm("mov.b64 %0, {%1, %2};" : "=l"(d) : "f"(x), "f"(y));
    return d;
}
__device__ __forceinline__ float2 unpack2(ull v) {
    float2 r;
    asm("mov.b64 {%0, %1}, %2;" : "=f"(r.x), "=f"(r.y) : "l"(v));
    return r;
}
__device__ __forceinline__ float rcp_approx(float x) {
    float r;
    asm("rcp.approx.f32 %0, %1;" : "=f"(r) : "f"(x));
    return r;
}

// Exact-enough gelu: erf via Abramowitz-Stegun 7.1.26 (|err| < 1.5e-7),
// branch-free: 1 MUFU.RCP + 5 FMA poly + MUFU.EX2.
__device__ __forceinline__ float gelu_exact(float x) {
    float xs = x * 0.70710678118654752f;   // erf argument
    float ax = fabsf(xs);
    float t = rcp_approx(fmaf(0.3275911f, ax, 1.0f));
    float p = 1.061405429f;
    p = fmaf(p, t, -1.453152027f);
    p = fmaf(p, t, 1.421413741f);
    p = fmaf(p, t, -0.284496736f);
    p = fmaf(p, t, 0.254829592f);
    p = p * t;
    float e = __expf(-ax * ax);
    float er = fmaf(-p, e, 1.0f);
    er = copysignf(er, xs);
    return 0.5f * x * (1.0f + er);
}

// ---------------------------------------------------------------------------
// GEMM: C[m][n] = sum_k A[m][k] * W[n][k] (+ bias[n])
// BM=128, BN=128, BK=16, 256 threads, 8x8 per-thread microtile, FFMA2 inner.
// ---------------------------------------------------------------------------
__global__ __launch_bounds__(256) void gemm_nt(
    const float* __restrict__ A, const float* __restrict__ W,
    const float* __restrict__ bias, float* __restrict__ C,
    int M, int Nc, int K)
{
    __shared__ float As[16][132];
    __shared__ float Bs[16][132];
    const int tid = threadIdx.x;
    const int ty = tid >> 4, tx = tid & 15;
    const int brow = blockIdx.y * 128, bcol = blockIdx.x * 128;

    ull acc2[8][4];
#pragma unroll
    for (int i2 = 0; i2 < 8; i2++)
#pragma unroll
        for (int j2 = 0; j2 < 4; j2++) acc2[i2][j2] = 0ull;

    for (int k0 = 0; k0 < K; k0 += 16) {
#pragma unroll
        for (int t = tid; t < 512; t += 256) {
            int m = t >> 2, kq = (t & 3) * 4;
            float4 f = *(const float4*)(A + (size_t)(brow + m) * K + k0 + kq);
            As[kq + 0][m] = f.x; As[kq + 1][m] = f.y;
            As[kq + 2][m] = f.z; As[kq + 3][m] = f.w;
        }
#pragma unroll
        for (int t = tid; t < 512; t += 256) {
            int n = t >> 2, kq = (t & 3) * 4;
            float4 f = *(const float4*)(W + (size_t)(bcol + n) * K + k0 + kq);
            Bs[kq + 0][n] = f.x; Bs[kq + 1][n] = f.y;
            Bs[kq + 2][n] = f.z; Bs[kq + 3][n] = f.w;
        }
        __syncthreads();
#pragma unroll
        for (int kk = 0; kk < 16; kk++) {
            float4 a0 = *(const float4*)&As[kk][ty * 8];
            float4 a1 = *(const float4*)&As[kk][ty * 8 + 4];
            ulonglong2 bq0 = *(const ulonglong2*)&Bs[kk][tx * 8];
            ulonglong2 bq1 = *(const ulonglong2*)&Bs[kk][tx * 8 + 4];
            ull bp0 = bq0.x, bp1 = bq0.y, bp2 = bq1.x, bp3 = bq1.y;
            float av[8] = {a0.x, a0.y, a0.z, a0.w, a1.x, a1.y, a1.z, a1.w};
#pragma unroll
            for (int i2 = 0; i2 < 8; i2++) {
                ull aa = pack2(av[i2], av[i2]);
                acc2[i2][0] = ffma2(aa, bp0, acc2[i2][0]);
                acc2[i2][1] = ffma2(aa, bp1, acc2[i2][1]);
                acc2[i2][2] = ffma2(aa, bp2, acc2[i2][2]);
                acc2[i2][3] = ffma2(aa, bp3, acc2[i2][3]);
            }
        }
        __syncthreads();
    }

#pragma unroll
    for (int i2 = 0; i2 < 8; i2++) {
        int row = brow + ty * 8 + i2;
        int col = bcol + tx * 8;
        float2 c0 = unpack2(acc2[i2][0]);
        float2 c1 = unpack2(acc2[i2][1]);
        float2 c2 = unpack2(acc2[i2][2]);
        float2 c3 = unpack2(acc2[i2][3]);
        float4 lo, hi;
        lo.x = c0.x; lo.y = c0.y; lo.z = c1.x; lo.w = c1.y;
        hi.x = c2.x; hi.y = c2.y; hi.z = c3.x; hi.w = c3.y;
        if (bias) {
            lo.x += bias[col + 0]; lo.y += bias[col + 1];
            lo.z += bias[col + 2]; lo.w += bias[col + 3];
            hi.x += bias[col + 4]; hi.y += bias[col + 5];
            hi.z += bias[col + 6]; hi.w += bias[col + 7];
        }
        *(float4*)(C + (size_t)row * Nc + col) = lo;
        *(float4*)(C + (size_t)row * Nc + col + 4) = hi;
    }
}

// ---------------------------------------------------------------------------
// Fused relative-position-bias attention (v2).
// Grid: B * (N/32) blocks, 512 threads.
// warp w = tid>>5: h = w>>1, i-block = (w&1)*16.
// lane: i = iblk + (lane&15), half = lane>>4 (owns 32 of 64 head dims).
// Partner halves combine QK dots via shfl.xor(16) within the warp.
// j-tiles of 32 staged in SMEM; bias MLP shared across heads; FFMA2 math.
// ---------------------------------------------------------------------------
__global__ __launch_bounds__(512) void attn_bias_kernel(
    const float* __restrict__ qkv, const float* __restrict__ coords,
    const unsigned char* __restrict__ kpm,
    const float* __restrict__ w1, const float* __restrict__ b1,
    const float* __restrict__ w2, const float* __restrict__ b2,
    const float* __restrict__ cscales, const float* __restrict__ alphap,
    float* __restrict__ outp)
{
    extern __shared__ float sm[];
    float* k_s    = sm;              // 32 * 512
    float* v_s    = sm + 16384;      // 32 * 512
    float* bias_s = sm + 32768;      // 32(j) * 8(h) * 32(i)
    float* ci_s   = sm + 40960;      // 32 * 4
    float* cj_s   = sm + 41088;      // 32 * 4
    float* w1ps   = sm + 41216;      // 4 feat * 16 upairs * 2 = 128
    float* w2ps   = sm + 41344;      // 32 units * 4 hpairs * 2 = 256 (alpha folded)
    float* b1s    = sm + 41600;      // 32
    float* b2a    = sm + 41632;      // 8 (alpha folded)
    float* mask_s = sm + 41640;      // 32

    const int tid  = threadIdx.x;
    const int lane = tid & 31;
    const int w    = tid >> 5;
    const int h    = w >> 1;
    const int i    = (w & 1) * 16 + (lane & 15);
    const int half = lane >> 4;
    const int b    = blockIdx.x >> 5;
    const int i0   = (blockIdx.x & 31) * 32;
    const float alpha = alphap[0];

    if (tid < 64) {
        int f = tid >> 4, u = tid & 15;
        w1ps[f * 32 + 2 * u]     = w1[(2 * u) * 4 + f];
        w1ps[f * 32 + 2 * u + 1] = w1[(2 * u + 1) * 4 + f];
    }
    if (tid < 128) {
        int u = tid >> 2, hp = tid & 3;
        w2ps[u * 8 + 2 * hp]     = alpha * w2[(2 * hp) * 32 + u];
        w2ps[u * 8 + 2 * hp + 1] = alpha * w2[(2 * hp + 1) * 32 + u];
    }
    if (tid < 32) b1s[tid] = b1[tid];
    if (tid < 8)  b2a[tid] = alpha * b2[tid];
    if (tid < 32) {
        int ig = i0 + tid;
        ci_s[tid * 4 + 0] = coords[((size_t)b * NN + ig) * 3 + 0] / cscales[0];
        ci_s[tid * 4 + 1] = coords[((size_t)b * NN + ig) * 3 + 1] / cscales[1];
        ci_s[tid * 4 + 2] = coords[((size_t)b * NN + ig) * 3 + 2] / cscales[2];
        ci_s[tid * 4 + 3] = 0.f;
    }

    // q (pre-scaled by 1/8), this thread's 32 dims, packed f32x2.
    ull q2[16];
    {
        const float4* qp = (const float4*)(qkv
            + ((size_t)(b * NN + i0 + i)) * 1536 + h * 64 + half * 32);
#pragma unroll
        for (int t = 0; t < 8; t++) {
            float4 f = qp[t];
            q2[2 * t]     = pack2(f.x * 0.125f, f.y * 0.125f);
            q2[2 * t + 1] = pack2(f.z * 0.125f, f.w * 0.125f);
        }
    }

    ull acc2[16];
#pragma unroll
    for (int d = 0; d < 16; d++) acc2[d] = 0ull;
    float mrun = -INFINITY, l = 0.f;

    __syncthreads();

    for (int j0 = 0; j0 < NN; j0 += 32) {
        // ---- stage K/V tile ----
#pragma unroll
        for (int t = tid; t < 4096; t += 512) {
            int jj = t >> 7, c4 = t & 127;
            const float4* src =
                (const float4*)(qkv + ((size_t)(b * NN + j0 + jj)) * 1536);
            ((float4*)k_s)[jj * 128 + c4] = src[128 + c4];
            ((float4*)v_s)[jj * 128 + c4] = src[256 + c4];
        }
        if (tid < 32) {
            int jg = j0 + tid;
            mask_s[tid] = kpm[(size_t)b * NN + jg] ? 1.f : 0.f;
            cj_s[tid * 4 + 0] = coords[((size_t)b * NN + jg) * 3 + 0] / cscales[0];
            cj_s[tid * 4 + 1] = coords[((size_t)b * NN + jg) * 3 + 1] / cscales[1];
            cj_s[tid * 4 + 2] = coords[((size_t)b * NN + jg) * 3 + 2] / cscales[2];
            cj_s[tid * 4 + 3] = 0.f;
        }
        __syncthreads();

        // ---- Phase A: pairwise bias MLP, 2 pairs/thread, FFMA2 over unit pairs ----
        {
            const ull* w1x = (const ull*)(w1ps);
            const ull* w1y = (const ull*)(w1ps + 32);
            const ull* w1z = (const ull*)(w1ps + 64);
            const ull* w1d = (const ull*)(w1ps + 96);
            const ull* b1u = (const ull*)b1s;
            const ull* w2u = (const ull*)w2ps;   // [unit][hp]
            const ull* b2u = (const ull*)b2a;
#pragma unroll
            for (int pp = 0; pp < 2; pp++) {
                int p  = tid + 512 * pp;
                int jj = p >> 5, ii = p & 31;
                float dx = ci_s[ii * 4 + 0] - cj_s[jj * 4 + 0];
                float dy = ci_s[ii * 4 + 1] - cj_s[jj * 4 + 1];
                float dz = ci_s[ii * 4 + 2] - cj_s[jj * 4 + 2];
                float dist = sqrtf(dx * dx + dy * dy + dz * dz);
                ull dx2 = pack2(dx, dx), dy2 = pack2(dy, dy);
                ull dz2 = pack2(dz, dz), di2 = pack2(dist, dist);
                ull bo0 = b2u[0], bo1 = b2u[1], bo2r = b2u[2], bo3 = b2u[3];
#pragma unroll
                for (int u = 0; u < 16; u++) {
                    ull t2 = b1u[u];
                    t2 = ffma2(w1x[u], dx2, t2);
                    t2 = ffma2(w1y[u], dy2, t2);
                    t2 = ffma2(w1z[u], dz2, t2);
                    t2 = ffma2(w1d[u], di2, t2);
                    float2 tv = unpack2(t2);
                    float g0 = gelu_exact(tv.x);
                    float g1 = gelu_exact(tv.y);
                    ull g02 = pack2(g0, g0), g12 = pack2(g1, g1);
                    const ull* wa = w2u + (2 * u) * 4;
                    const ull* wb = w2u + (2 * u + 1) * 4;
                    bo0  = ffma2(g02, wa[0], bo0);
                    bo1  = ffma2(g02, wa[1], bo1);
                    bo2r = ffma2(g02, wa[2], bo2r);
                    bo3  = ffma2(g02, wa[3], bo3);
                    bo0  = ffma2(g12, wb[0], bo0);
                    bo1  = ffma2(g12, wb[1], bo1);
                    bo2r = ffma2(g12, wb[2], bo2r);
                    bo3  = ffma2(g12, wb[3], bo3);
                }
                float zf = ((i0 + ii) >= NS_TOK && (j0 + jj) >= NS_TOK) ? 1.f : 0.f;
                float2 v0 = unpack2(bo0), v1 = unpack2(bo1);
                float2 v2 = unpack2(bo2r), v3 = unpack2(bo3);
                float* bp = bias_s + jj * 256 + ii;
                bp[0 * 32]  = v0.x * zf; bp[1 * 32] = v0.y * zf;
                bp[2 * 32]  = v1.x * zf; bp[3 * 32] = v1.y * zf;
                bp[4 * 32]  = v2.x * zf; bp[5 * 32] = v2.y * zf;
                bp[6 * 32]  = v3.x * zf; bp[7 * 32] = v3.y * zf;
            }
        }
        __syncthreads();

        // ---- Phase B: logits + online softmax + AV ----
        float tmax = -INFINITY;
#pragma unroll 4
        for (int jj = 0; jj < 32; jj++) {
            const ulonglong2* kp =
                (const ulonglong2*)(k_s + jj * 512 + h * 64 + half * 32);
            ull s0 = 0ull, s1 = 0ull, s2 = 0ull, s3 = 0ull;
#pragma unroll
            for (int t = 0; t < 4; t++) {
                ulonglong2 ka = kp[2 * t], kb = kp[2 * t + 1];
                s0 = ffma2(q2[4 * t + 0], ka.x, s0);
                s1 = ffma2(q2[4 * t + 1], ka.y, s1);
                s2 = ffma2(q2[4 * t + 2], kb.x, s2);
                s3 = ffma2(q2[4 * t + 3], kb.y, s3);
            }
            s0 = fadd2(fadd2(s0, s1), fadd2(s2, s3));
            float2 sv = unpack2(s0);
            float dot = sv.x + sv.y;
            dot += __shfl_xor_sync(0xffffffffu, dot, 16);
            float lgv = dot + bias_s[jj * 256 + h * 32 + i];
            if (mask_s[jj] > 0.5f) lgv = -1e30f;
            bias_s[jj * 256 + h * 32 + i] = lgv;   // scratch (both halves: same val)
            tmax = fmaxf(tmax, lgv);
        }
        float mnew = fmaxf(mrun, tmax);
        float corr = __expf(mrun - mnew);
        mrun = mnew;
        l *= corr;
        {
            ull c2 = pack2(corr, corr);
#pragma unroll
            for (int d = 0; d < 16; d++) acc2[d] = fmul2(acc2[d], c2);
        }
#pragma unroll 4
        for (int jj = 0; jj < 32; jj++) {
            float p = __expf(bias_s[jj * 256 + h * 32 + i] - mrun);
            l += p;
            ull p2 = pack2(p, p);
            const ulonglong2* vp =
                (const ulonglong2*)(v_s + jj * 512 + h * 64 + half * 32);
#pragma unroll
            for (int t = 0; t < 8; t++) {
                ulonglong2 va = vp[t];
                acc2[2 * t]     = ffma2(p2, va.x, acc2[2 * t]);
                acc2[2 * t + 1] = ffma2(p2, va.y, acc2[2 * t + 1]);
            }
        }
        __syncthreads();
    }

    float invl = 1.f / l;
    float* op = outp + ((size_t)(b * NN + i0 + i)) * 512 + h * 64 + half * 32;
#pragma unroll
    for (int t = 0; t < 8; t++) {
        float2 e0 = unpack2(acc2[2 * t]);
        float2 e1 = unpack2(acc2[2 * t + 1]);
        float4 f;
        f.x = e0.x * invl; f.y = e0.y * invl;
        f.z = e1.x * invl; f.w = e1.y * invl;
        ((float4*)op)[t] = f;
    }
}

// ---------------------------------------------------------------------------
extern "C" void kernel_launch(void* const* d_in, const int* in_sizes, int n_in,
                              void* d_out, int out_size)
{
    const float* x      = (const float*)d_in[0];
    const float* coords = (const float*)d_in[1];
    const unsigned char* kpm = (const unsigned char*)d_in[2];
    const float* qkv_w  = (const float*)d_in[3];
    const float* out_w  = (const float*)d_in[4];
    const float* out_b  = (const float*)d_in[5];
    const float* alpha  = (const float*)d_in[6];
    const float* w1     = (const float*)d_in[7];
    const float* b1     = (const float*)d_in[8];
    const float* w2     = (const float*)d_in[9];
    const float* b2     = (const float*)d_in[10];
    const float* cs     = (const float*)d_in[11];
    float* out = (float*)d_out;

    float* qkvp = nullptr;
    float* attnp = nullptr;
    cudaGetSymbolAddress((void**)&qkvp, g_qkv);
    cudaGetSymbolAddress((void**)&attnp, g_attn);

    const int SMEM = 41672 * 4;  // ~163 KB
    cudaFuncSetAttribute(attn_bias_kernel,
                         cudaFuncAttributeMaxDynamicSharedMemorySize, SMEM);

    // 1) QKV projection: [8192,512] @ [512,1536]
    dim3 g1(1536 / 128, 8192 / 128);
    gemm_nt<<<g1, 256>>>(x, qkv_w, nullptr, qkvp, BB * NN, 3 * DM, DM);

    // 2) Fused bias + attention
    attn_bias_kernel<<<BB * (NN / 32), 512, SMEM>>>(
        qkvp, coords, kpm, w1, b1, w2, b2, cs, alpha, attnp);

    // 3) Output projection: [8192,512] @ [512,512] + bias
    dim3 g3(512 / 128, 8192 / 128);
    gemm_nt<<<g3, 256>>>(attnp, out_w, out_b, out, BB * NN, DM, DM);
}

// round 3
// speedup vs baseline: 1.8259x; 1.8259x over previous
#include <cuda_runtime.h>
#include <math.h>

#define BB 8
#define NN 1024
#define DM 512
#define NH 8
#define HD 64
#define NS_TOK 1

typedef unsigned long long ull;

// Scratch (device globals: no allocations allowed in kernel_launch)
__device__ float g_qkv[(size_t)BB * NN * 3 * DM];   // [b][n][1536] : q|k|v
__device__ float g_attn[(size_t)BB * NN * DM];      // [b][n][512]

// ---------------------------------------------------------------------------
// Packed f32x2 helpers -- used ONLY in the GEMM (measured win there).
// ---------------------------------------------------------------------------
__device__ __forceinline__ ull ffma2(ull a, ull b, ull c) {
    ull d;
    asm("fma.rn.f32x2 %0, %1, %2, %3;" : "=l"(d) : "l"(a), "l"(b), "l"(c));
    return d;
}
__device__ __forceinline__ ull pack2(float x, float y) {
    ull d;
    asm("mov.b64 %0, {%1, %2};" : "=l"(d) : "f"(x), "f"(y));
    return d;
}
__device__ __forceinline__ float2 unpack2(ull v) {
    float2 r;
    asm("mov.b64 {%0, %1}, %2;" : "=f"(r.x), "=f"(r.y) : "l"(v));
    return r;
}
__device__ __forceinline__ float rcp_approx(float x) {
    float r;
    asm("rcp.approx.f32 %0, %1;" : "=f"(r) : "f"(x));
    return r;
}

// Exact-enough gelu: erf via Abramowitz-Stegun 7.1.26 (|err| < 1.5e-7),
// branch-free. Validated in round 2 (rel_err stayed 9.5e-7).
__device__ __forceinline__ float gelu_exact(float x) {
    float xs = x * 0.70710678118654752f;
    float ax = fabsf(xs);
    float t = rcp_approx(fmaf(0.3275911f, ax, 1.0f));
    float p = 1.061405429f;
    p = fmaf(p, t, -1.453152027f);
    p = fmaf(p, t, 1.421413741f);
    p = fmaf(p, t, -0.284496736f);
    p = fmaf(p, t, 0.254829592f);
    p = p * t;
    float e = __expf(-ax * ax);
    float er = fmaf(-p, e, 1.0f);
    er = copysignf(er, xs);
    return 0.5f * x * (1.0f + er);
}

// ---------------------------------------------------------------------------
// GEMM: C[m][n] = sum_k A[m][k] * W[n][k] (+ bias[n])
// BM=128, BN=128, BK=16, 256 threads, 8x8 microtile, FFMA2 inner (round-2,
// measured 325us on the QKV shape).
// ---------------------------------------------------------------------------
__global__ __launch_bounds__(256) void gemm_nt(
    const float* __restrict__ A, const float* __restrict__ W,
    const float* __restrict__ bias, float* __restrict__ C,
    int M, int Nc, int K)
{
    __shared__ float As[16][132];
    __shared__ float Bs[16][132];
    const int tid = threadIdx.x;
    const int ty = tid >> 4, tx = tid & 15;
    const int brow = blockIdx.y * 128, bcol = blockIdx.x * 128;

    ull acc2[8][4];
#pragma unroll
    for (int i2 = 0; i2 < 8; i2++)
#pragma unroll
        for (int j2 = 0; j2 < 4; j2++) acc2[i2][j2] = 0ull;

    for (int k0 = 0; k0 < K; k0 += 16) {
#pragma unroll
        for (int t = tid; t < 512; t += 256) {
            int m = t >> 2, kq = (t & 3) * 4;
            float4 f = *(const float4*)(A + (size_t)(brow + m) * K + k0 + kq);
            As[kq + 0][m] = f.x; As[kq + 1][m] = f.y;
            As[kq + 2][m] = f.z; As[kq + 3][m] = f.w;
        }
#pragma unroll
        for (int t = tid; t < 512; t += 256) {
            int n = t >> 2, kq = (t & 3) * 4;
            float4 f = *(const float4*)(W + (size_t)(bcol + n) * K + k0 + kq);
            Bs[kq + 0][n] = f.x; Bs[kq + 1][n] = f.y;
            Bs[kq + 2][n] = f.z; Bs[kq + 3][n] = f.w;
        }
        __syncthreads();
#pragma unroll
        for (int kk = 0; kk < 16; kk++) {
            float4 a0 = *(const float4*)&As[kk][ty * 8];
            float4 a1 = *(const float4*)&As[kk][ty * 8 + 4];
            ulonglong2 bq0 = *(const ulonglong2*)&Bs[kk][tx * 8];
            ulonglong2 bq1 = *(const ulonglong2*)&Bs[kk][tx * 8 + 4];
            ull bp0 = bq0.x, bp1 = bq0.y, bp2 = bq1.x, bp3 = bq1.y;
            float av[8] = {a0.x, a0.y, a0.z, a0.w, a1.x, a1.y, a1.z, a1.w};
#pragma unroll
            for (int i2 = 0; i2 < 8; i2++) {
                ull aa = pack2(av[i2], av[i2]);
                acc2[i2][0] = ffma2(aa, bp0, acc2[i2][0]);
                acc2[i2][1] = ffma2(aa, bp1, acc2[i2][1]);
                acc2[i2][2] = ffma2(aa, bp2, acc2[i2][2]);
                acc2[i2][3] = ffma2(aa, bp3, acc2[i2][3]);
            }
        }
        __syncthreads();
    }

#pragma unroll
    for (int i2 = 0; i2 < 8; i2++) {
        int row = brow + ty * 8 + i2;
        int col = bcol + tx * 8;
        float2 c0 = unpack2(acc2[i2][0]);
        float2 c1 = unpack2(acc2[i2][1]);
        float2 c2 = unpack2(acc2[i2][2]);
        float2 c3 = unpack2(acc2[i2][3]);
        float4 lo, hi;
        lo.x = c0.x; lo.y = c0.y; lo.z = c1.x; lo.w = c1.y;
        hi.x = c2.x; hi.y = c2.y; hi.z = c3.x; hi.w = c3.y;
        if (bias) {
            lo.x += bias[col + 0]; lo.y += bias[col + 1];
            lo.z += bias[col + 2]; lo.w += bias[col + 3];
            hi.x += bias[col + 4]; hi.y += bias[col + 5];
            hi.z += bias[col + 6]; hi.w += bias[col + 7];
        }
        *(float4*)(C + (size_t)row * Nc + col) = lo;
        *(float4*)(C + (size_t)row * Nc + col + 4) = hi;
    }
}

// ---------------------------------------------------------------------------
// Fused relative-position-bias attention (v3: scalar fp32, 512 threads).
// Grid: B * (N/32) blocks, 512 threads (16 warps).
// warp w = tid>>5: h = w>>1, i-block = (w&1)*16.
// lane: i = iblk + (lane&15), half = lane>>4 (owns 32 of the 64 head dims).
// Partner halves combine QK dots via shfl.xor(16) within the warp.
// alpha folded into w2/b2 at load time.
// ---------------------------------------------------------------------------
__global__ __launch_bounds__(512) void attn_bias_kernel(
    const float* __restrict__ qkv, const float* __restrict__ coords,
    const unsigned char* __restrict__ kpm,
    const float* __restrict__ w1, const float* __restrict__ b1,
    const float* __restrict__ w2, const float* __restrict__ b2,
    const float* __restrict__ cscales, const float* __restrict__ alphap,
    float* __restrict__ outp)
{
    extern __shared__ float sm[];
    float* k_s    = sm;              // 32 * 512
    float* v_s    = sm + 16384;      // 32 * 512
    float* bias_s = sm + 32768;      // 32(j) * 8(h) * 32(i)
    float* ci_s   = sm + 40960;      // 32 * 4
    float* cj_s   = sm + 41088;      // 32 * 4
    float* w1_s   = sm + 41216;      // 32 * 4
    float* b1_s   = sm + 41344;      // 32
    float* w2_s   = sm + 41376;      // 8 * 32 (alpha folded)
    float* b2_s   = sm + 41632;      // 8 (alpha folded)
    float* mask_s = sm + 41640;      // 32

    const int tid  = threadIdx.x;
    const int lane = tid & 31;
    const int w    = tid >> 5;
    const int h    = w >> 1;
    const int i    = (w & 1) * 16 + (lane & 15);
    const int half = lane >> 4;
    const int b    = blockIdx.x >> 5;
    const int i0   = (blockIdx.x & 31) * 32;
    const float alpha = alphap[0];

    if (tid < 128) w1_s[tid] = w1[tid];
    if (tid < 32)  b1_s[tid] = b1[tid];
    if (tid < 256) w2_s[tid] = alpha * w2[tid];
    if (tid < 8)   b2_s[tid] = alpha * b2[tid];
    if (tid < 32) {
        int ig = i0 + tid;
        ci_s[tid * 4 + 0] = coords[((size_t)b * NN + ig) * 3 + 0] / cscales[0];
        ci_s[tid * 4 + 1] = coords[((size_t)b * NN + ig) * 3 + 1] / cscales[1];
        ci_s[tid * 4 + 2] = coords[((size_t)b * NN + ig) * 3 + 2] / cscales[2];
        ci_s[tid * 4 + 3] = 0.f;
    }

    // q (pre-scaled by 1/8): this thread's 32 dims.
    float q[32];
    {
        const float4* qp = (const float4*)(qkv
            + ((size_t)(b * NN + i0 + i)) * 1536 + h * 64 + half * 32);
#pragma unroll
        for (int t = 0; t < 8; t++) {
            float4 f = qp[t];
            q[4*t+0] = f.x * 0.125f; q[4*t+1] = f.y * 0.125f;
            q[4*t+2] = f.z * 0.125f; q[4*t+3] = f.w * 0.125f;
        }
    }

    float acc[32];
#pragma unroll
    for (int d = 0; d < 32; d++) acc[d] = 0.f;
    float mrun = -INFINITY, l = 0.f;

    __syncthreads();

    for (int j0 = 0; j0 < NN; j0 += 32) {
        // ---- stage K/V tile (rows j0..j0+31, all heads) ----
#pragma unroll
        for (int t = tid; t < 4096; t += 512) {
            int jj = t >> 7, c4 = t & 127;
            const float4* src =
                (const float4*)(qkv + ((size_t)(b * NN + j0 + jj)) * 1536);
            ((float4*)k_s)[jj * 128 + c4] = src[128 + c4];
            ((float4*)v_s)[jj * 128 + c4] = src[256 + c4];
        }
        if (tid < 32) {
            int jg = j0 + tid;
            mask_s[tid] = kpm[(size_t)b * NN + jg] ? 1.f : 0.f;
            cj_s[tid * 4 + 0] = coords[((size_t)b * NN + jg) * 3 + 0] / cscales[0];
            cj_s[tid * 4 + 1] = coords[((size_t)b * NN + jg) * 3 + 1] / cscales[1];
            cj_s[tid * 4 + 2] = coords[((size_t)b * NN + jg) * 3 + 2] / cscales[2];
            cj_s[tid * 4 + 3] = 0.f;
        }
        __syncthreads();

        // ---- Phase A: pairwise bias MLP (shared across heads), 2 pairs/thread ----
#pragma unroll 1
        for (int pp = 0; pp < 2; pp++) {
            int p  = tid + 512 * pp;
            int jj = p >> 5, ii = p & 31;
            float dx = ci_s[ii * 4 + 0] - cj_s[jj * 4 + 0];
            float dy = ci_s[ii * 4 + 1] - cj_s[jj * 4 + 1];
            float dz = ci_s[ii * 4 + 2] - cj_s[jj * 4 + 2];
            float dist = sqrtf(dx * dx + dy * dy + dz * dz);
            float bo[8];
#pragma unroll
            for (int hh = 0; hh < 8; hh++) bo[hh] = b2_s[hh];
#pragma unroll 4
            for (int kk = 0; kk < 32; kk++) {
                float t2 = b1_s[kk];
                t2 = fmaf(w1_s[kk * 4 + 0], dx,   t2);
                t2 = fmaf(w1_s[kk * 4 + 1], dy,   t2);
                t2 = fmaf(w1_s[kk * 4 + 2], dz,   t2);
                t2 = fmaf(w1_s[kk * 4 + 3], dist, t2);
                float g = gelu_exact(t2);
#pragma unroll
                for (int hh = 0; hh < 8; hh++)
                    bo[hh] = fmaf(g, w2_s[hh * 32 + kk], bo[hh]);
            }
            float zf = ((i0 + ii) >= NS_TOK && (j0 + jj) >= NS_TOK) ? 1.f : 0.f;
#pragma unroll
            for (int hh = 0; hh < 8; hh++)
                bias_s[jj * 256 + hh * 32 + ii] = bo[hh] * zf;
        }
        __syncthreads();

        // ---- Phase B: logits + online softmax + AV ----
        float tmax = -INFINITY;
        for (int jj = 0; jj < 32; jj++) {
            const float4* kp =
                (const float4*)(k_s + jj * 512 + h * 64 + half * 32);
            float d0 = 0.f, d1 = 0.f, d2 = 0.f, d3 = 0.f;
#pragma unroll
            for (int t = 0; t < 8; t++) {
                float4 f = kp[t];
                d0 = fmaf(q[4*t+0], f.x, d0);
                d1 = fmaf(q[4*t+1], f.y, d1);
                d2 = fmaf(q[4*t+2], f.z, d2);
                d3 = fmaf(q[4*t+3], f.w, d3);
            }
            float dot = (d0 + d1) + (d2 + d3);
            dot += __shfl_xor_sync(0xffffffffu, dot, 16);
            float lgv = dot + bias_s[jj * 256 + h * 32 + i];
            if (mask_s[jj] > 0.5f) lgv = -1e30f;
            bias_s[jj * 256 + h * 32 + i] = lgv;  // both halves write same value
            tmax = fmaxf(tmax, lgv);
        }
        float mnew = fmaxf(mrun, tmax);
        float corr = __expf(mrun - mnew);
        mrun = mnew;
        l *= corr;
#pragma unroll
        for (int d = 0; d < 32; d++) acc[d] *= corr;

        for (int jj = 0; jj < 32; jj++) {
            float p = __expf(bias_s[jj * 256 + h * 32 + i] - mrun);
            l += p;
            const float4* vp =
                (const float4*)(v_s + jj * 512 + h * 64 + half * 32);
#pragma unroll
            for (int t = 0; t < 8; t++) {
                float4 f = vp[t];
                acc[4*t+0] = fmaf(p, f.x, acc[4*t+0]);
                acc[4*t+1] = fmaf(p, f.y, acc[4*t+1]);
                acc[4*t+2] = fmaf(p, f.z, acc[4*t+2]);
                acc[4*t+3] = fmaf(p, f.w, acc[4*t+3]);
            }
        }
        __syncthreads();
    }

    float invl = 1.f / l;
    float* op = outp + ((size_t)(b * NN + i0 + i)) * 512 + h * 64 + half * 32;
#pragma unroll
    for (int t = 0; t < 8; t++) {
        float4 f;
        f.x = acc[4*t+0] * invl; f.y = acc[4*t+1] * invl;
        f.z = acc[4*t+2] * invl; f.w = acc[4*t+3] * invl;
        ((float4*)op)[t] = f;
    }
}

// ---------------------------------------------------------------------------
extern "C" void kernel_launch(void* const* d_in, const int* in_sizes, int n_in,
                              void* d_out, int out_size)
{
    const float* x      = (const float*)d_in[0];
    const float* coords = (const float*)d_in[1];
    const unsigned char* kpm = (const unsigned char*)d_in[2];
    const float* qkv_w  = (const float*)d_in[3];
    const float* out_w  = (const float*)d_in[4];
    const float* out_b  = (const float*)d_in[5];
    const float* alpha  = (const float*)d_in[6];
    const float* w1     = (const float*)d_in[7];
    const float* b1     = (const float*)d_in[8];
    const float* w2     = (const float*)d_in[9];
    const float* b2     = (const float*)d_in[10];
    const float* cs     = (const float*)d_in[11];
    float* out = (float*)d_out;

    float* qkvp = nullptr;
    float* attnp = nullptr;
    cudaGetSymbolAddress((void**)&qkvp, g_qkv);
    cudaGetSymbolAddress((void**)&attnp, g_attn);

    const int SMEM = 41672 * 4;  // ~163 KB
    cudaFuncSetAttribute(attn_bias_kernel,
                         cudaFuncAttributeMaxDynamicSharedMemorySize, SMEM);

    // 1) QKV projection: [8192,512] @ [512,1536]
    dim3 g1(1536 / 128, 8192 / 128);
    gemm_nt<<<g1, 256>>>(x, qkv_w, nullptr, qkvp, BB * NN, 3 * DM, DM);

    // 2) Fused bias + attention
    attn_bias_kernel<<<BB * (NN / 32), 512, SMEM>>>(
        qkvp, coords, kpm, w1, b1, w2, b2, cs, alpha, attnp);

    // 3) Output projection: [8192,512] @ [512,512] + bias
    dim3 g3(512 / 128, 8192 / 128);
    gemm_nt<<<g3, 256>>>(attnp, out_w, out_b, out, BB * NN, DM, DM);
}

// round 4
// speedup vs baseline: 1.9411x; 1.0631x over previous
#include <cuda_runtime.h>
#include <math.h>

#define BB 8
#define NN 1024
#define DM 512
#define NH 8
#define HD 64
#define NS_TOK 1

// Scratch (device globals: no allocations allowed in kernel_launch)
__device__ float g_qkv[(size_t)BB * NN * 3 * DM];   // [b][n][1536] : q|k|v
__device__ float g_attn[(size_t)BB * NN * DM];      // [b][n][512]

// ---------------------------------------------------------------------------
// tf32 split-precision helpers
// ---------------------------------------------------------------------------
__device__ __forceinline__ unsigned cvt_tf32(float x) {
    unsigned r;
    asm("cvt.rna.tf32.f32 %0, %1;" : "=r"(r) : "f"(x));
    return r;
}
__device__ __forceinline__ void split_tf32(float x, unsigned& hi, unsigned& lo) {
    hi = cvt_tf32(x);
    float rem = x - __uint_as_float(hi);
    lo = cvt_tf32(rem);
}
__device__ __forceinline__ void mma_tf32(
    float& c0, float& c1, float& c2, float& c3,
    unsigned a0, unsigned a1, unsigned a2, unsigned a3,
    unsigned b0, unsigned b1)
{
    asm("mma.sync.aligned.m16n8k8.row.col.f32.tf32.tf32.f32 "
        "{%0,%1,%2,%3}, {%4,%5,%6,%7}, {%8,%9}, {%0,%1,%2,%3};"
        : "+f"(c0), "+f"(c1), "+f"(c2), "+f"(c3)
        : "r"(a0), "r"(a1), "r"(a2), "r"(a3), "r"(b0), "r"(b1));
}

__device__ __forceinline__ float rcp_approx(float x) {
    float r;
    asm("rcp.approx.f32 %0, %1;" : "=f"(r) : "f"(x));
    return r;
}

// Exact-enough gelu: erf via Abramowitz-Stegun 7.1.26 (|err| < 1.5e-7),
// branch-free. Validated rounds 2-3 (rel_err stays 9.5e-7).
__device__ __forceinline__ float gelu_exact(float x) {
    float xs = x * 0.70710678118654752f;
    float ax = fabsf(xs);
    float t = rcp_approx(fmaf(0.3275911f, ax, 1.0f));
    float p = 1.061405429f;
    p = fmaf(p, t, -1.453152027f);
    p = fmaf(p, t, 1.421413741f);
    p = fmaf(p, t, -0.284496736f);
    p = fmaf(p, t, 0.254829592f);
    p = p * t;
    float e = __expf(-ax * ax);
    float er = fmaf(-p, e, 1.0f);
    er = copysignf(er, xs);
    return 0.5f * x * (1.0f + er);
}

// ---------------------------------------------------------------------------
// Tensor-core GEMM (tf32 split, fp32-class accuracy):
// C[m][n] = sum_k A[m][k] * W[n][k] (+ bias[n])
// BM=128, BN=128, BK=16, 256 threads (8 warps, 2x4 grid, 64x32 warp tiles).
// Each fragment product done as Ah*Bh + Ah*Bl + Al*Bh (3x m16n8k8 MMA).
// ---------------------------------------------------------------------------
#define ROWPAD 20   // floats per smem row (16 data + 4 pad): conflict-free frags

__global__ __launch_bounds__(256) void gemm_tc(
    const float* __restrict__ A, const float* __restrict__ W,
    const float* __restrict__ bias, float* __restrict__ C,
    int M, int Nc, int K)
{
    __shared__ float As[128 * ROWPAD];
    __shared__ float Ws[128 * ROWPAD];
    const int tid  = threadIdx.x;
    const int wid  = tid >> 5, lane = tid & 31;
    const int g    = lane >> 2, t4 = lane & 3;
    const int wm   = wid & 1,  wn  = wid >> 1;     // 2 (m) x 4 (n) warps
    const int brow = blockIdx.y * 128, bcol = blockIdx.x * 128;
    const int m_base = wm * 64, n_base = wn * 32;

    float c[4][4][4];
#pragma unroll
    for (int mf = 0; mf < 4; mf++)
#pragma unroll
        for (int nf = 0; nf < 4; nf++)
#pragma unroll
            for (int r = 0; r < 4; r++) c[mf][nf][r] = 0.f;

    for (int k0 = 0; k0 < K; k0 += 16) {
        // stage A tile [128 m][16 k] and W tile [128 n][16 k], fp32, row-major
#pragma unroll
        for (int t = tid; t < 512; t += 256) {
            int m = t >> 2, kq = (t & 3) * 4;
            float4 f = *(const float4*)(A + (size_t)(brow + m) * K + k0 + kq);
            *(float4*)&As[m * ROWPAD + kq] = f;
        }
#pragma unroll
        for (int t = tid; t < 512; t += 256) {
            int n = t >> 2, kq = (t & 3) * 4;
            float4 f = *(const float4*)(W + (size_t)(bcol + n) * K + k0 + kq);
            *(float4*)&Ws[n * ROWPAD + kq] = f;
        }
        __syncthreads();

#pragma unroll
        for (int ks = 0; ks < 16; ks += 8) {
            // A fragments for 4 m-frags
            unsigned ah[4][4], al[4][4];
#pragma unroll
            for (int mf = 0; mf < 4; mf++) {
                int r0 = (m_base + mf * 16 + g) * ROWPAD;
                int r1 = r0 + 8 * ROWPAD;
                split_tf32(As[r0 + ks + t4],     ah[mf][0], al[mf][0]);
                split_tf32(As[r1 + ks + t4],     ah[mf][1], al[mf][1]);
                split_tf32(As[r0 + ks + t4 + 4], ah[mf][2], al[mf][2]);
                split_tf32(As[r1 + ks + t4 + 4], ah[mf][3], al[mf][3]);
            }
            // B fragments for 4 n-frags
            unsigned bh[4][2], bl[4][2];
#pragma unroll
            for (int nf = 0; nf < 4; nf++) {
                int rn = (n_base + nf * 8 + g) * ROWPAD;
                split_tf32(Ws[rn + ks + t4],     bh[nf][0], bl[nf][0]);
                split_tf32(Ws[rn + ks + t4 + 4], bh[nf][1], bl[nf][1]);
            }
#pragma unroll
            for (int mf = 0; mf < 4; mf++)
#pragma unroll
                for (int nf = 0; nf < 4; nf++) {
                    float* cc = c[mf][nf];
                    mma_tf32(cc[0], cc[1], cc[2], cc[3],
                             ah[mf][0], ah[mf][1], ah[mf][2], ah[mf][3],
                             bh[nf][0], bh[nf][1]);
                    mma_tf32(cc[0], cc[1], cc[2], cc[3],
                             ah[mf][0], ah[mf][1], ah[mf][2], ah[mf][3],
                             bl[nf][0], bl[nf][1]);
                    mma_tf32(cc[0], cc[1], cc[2], cc[3],
                             al[mf][0], al[mf][1], al[mf][2], al[mf][3],
                             bh[nf][0], bh[nf][1]);
                }
        }
        __syncthreads();
    }

    // epilogue
#pragma unroll
    for (int mf = 0; mf < 4; mf++) {
        int row0 = brow + m_base + mf * 16 + g;
#pragma unroll
        for (int nf = 0; nf < 4; nf++) {
            int col = bcol + n_base + nf * 8 + 2 * t4;
            float b0 = 0.f, b1 = 0.f;
            if (bias) { b0 = bias[col]; b1 = bias[col + 1]; }
            float2 lo, hi;
            lo.x = c[mf][nf][0] + b0; lo.y = c[mf][nf][1] + b1;
            hi.x = c[mf][nf][2] + b0; hi.y = c[mf][nf][3] + b1;
            *(float2*)(C + (size_t)row0 * Nc + col) = lo;
            *(float2*)(C + (size_t)(row0 + 8) * Nc + col) = hi;
        }
    }
}

// ---------------------------------------------------------------------------
// Fused relative-position-bias attention (v3: scalar fp32, 512 threads).
// UNCHANGED from round 3 (measured ~1200us component).
// ---------------------------------------------------------------------------
__global__ __launch_bounds__(512) void attn_bias_kernel(
    const float* __restrict__ qkv, const float* __restrict__ coords,
    const unsigned char* __restrict__ kpm,
    const float* __restrict__ w1, const float* __restrict__ b1,
    const float* __restrict__ w2, const float* __restrict__ b2,
    const float* __restrict__ cscales, const float* __restrict__ alphap,
    float* __restrict__ outp)
{
    extern __shared__ float sm[];
    float* k_s    = sm;              // 32 * 512
    float* v_s    = sm + 16384;      // 32 * 512
    float* bias_s = sm + 32768;      // 32(j) * 8(h) * 32(i)
    float* ci_s   = sm + 40960;      // 32 * 4
    float* cj_s   = sm + 41088;      // 32 * 4
    float* w1_s   = sm + 41216;      // 32 * 4
    float* b1_s   = sm + 41344;      // 32
    float* w2_s   = sm + 41376;      // 8 * 32 (alpha folded)
    float* b2_s   = sm + 41632;      // 8 (alpha folded)
    float* mask_s = sm + 41640;      // 32

    const int tid  = threadIdx.x;
    const int lane = tid & 31;
    const int w    = tid >> 5;
    const int h    = w >> 1;
    const int i    = (w & 1) * 16 + (lane & 15);
    const int half = lane >> 4;
    const int b    = blockIdx.x >> 5;
    const int i0   = (blockIdx.x & 31) * 32;
    const float alpha = alphap[0];

    if (tid < 128) w1_s[tid] = w1[tid];
    if (tid < 32)  b1_s[tid] = b1[tid];
    if (tid < 256) w2_s[tid] = alpha * w2[tid];
    if (tid < 8)   b2_s[tid] = alpha * b2[tid];
    if (tid < 32) {
        int ig = i0 + tid;
        ci_s[tid * 4 + 0] = coords[((size_t)b * NN + ig) * 3 + 0] / cscales[0];
        ci_s[tid * 4 + 1] = coords[((size_t)b * NN + ig) * 3 + 1] / cscales[1];
        ci_s[tid * 4 + 2] = coords[((size_t)b * NN + ig) * 3 + 2] / cscales[2];
        ci_s[tid * 4 + 3] = 0.f;
    }

    // q (pre-scaled by 1/8): this thread's 32 dims.
    float q[32];
    {
        const float4* qp = (const float4*)(qkv
            + ((size_t)(b * NN + i0 + i)) * 1536 + h * 64 + half * 32);
#pragma unroll
        for (int t = 0; t < 8; t++) {
            float4 f = qp[t];
            q[4*t+0] = f.x * 0.125f; q[4*t+1] = f.y * 0.125f;
            q[4*t+2] = f.z * 0.125f; q[4*t+3] = f.w * 0.125f;
        }
    }

    float acc[32];
#pragma unroll
    for (int d = 0; d < 32; d++) acc[d] = 0.f;
    float mrun = -INFINITY, l = 0.f;

    __syncthreads();

    for (int j0 = 0; j0 < NN; j0 += 32) {
        // ---- stage K/V tile (rows j0..j0+31, all heads) ----
#pragma unroll
        for (int t = tid; t < 4096; t += 512) {
            int jj = t >> 7, c4 = t & 127;
            const float4* src =
                (const float4*)(qkv + ((size_t)(b * NN + j0 + jj)) * 1536);
            ((float4*)k_s)[jj * 128 + c4] = src[128 + c4];
            ((float4*)v_s)[jj * 128 + c4] = src[256 + c4];
        }
        if (tid < 32) {
            int jg = j0 + tid;
            mask_s[tid] = kpm[(size_t)b * NN + jg] ? 1.f : 0.f;
            cj_s[tid * 4 + 0] = coords[((size_t)b * NN + jg) * 3 + 0] / cscales[0];
            cj_s[tid * 4 + 1] = coords[((size_t)b * NN + jg) * 3 + 1] / cscales[1];
            cj_s[tid * 4 + 2] = coords[((size_t)b * NN + jg) * 3 + 2] / cscales[2];
            cj_s[tid * 4 + 3] = 0.f;
        }
        __syncthreads();

        // ---- Phase A: pairwise bias MLP (shared across heads), 2 pairs/thread ----
#pragma unroll 1
        for (int pp = 0; pp < 2; pp++) {
            int p  = tid + 512 * pp;
            int jj = p >> 5, ii = p & 31;
            float dx = ci_s[ii * 4 + 0] - cj_s[jj * 4 + 0];
            float dy = ci_s[ii * 4 + 1] - cj_s[jj * 4 + 1];
            float dz = ci_s[ii * 4 + 2] - cj_s[jj * 4 + 2];
            float dist = sqrtf(dx * dx + dy * dy + dz * dz);
            float bo[8];
#pragma unroll
            for (int hh = 0; hh < 8; hh++) bo[hh] = b2_s[hh];
#pragma unroll 4
            for (int kk = 0; kk < 32; kk++) {
                float t2 = b1_s[kk];
                t2 = fmaf(w1_s[kk * 4 + 0], dx,   t2);
                t2 = fmaf(w1_s[kk * 4 + 1], dy,   t2);
                t2 = fmaf(w1_s[kk * 4 + 2], dz,   t2);
                t2 = fmaf(w1_s[kk * 4 + 3], dist, t2);
                float g = gelu_exact(t2);
#pragma unroll
                for (int hh = 0; hh < 8; hh++)
                    bo[hh] = fmaf(g, w2_s[hh * 32 + kk], bo[hh]);
            }
            float zf = ((i0 + ii) >= NS_TOK && (j0 + jj) >= NS_TOK) ? 1.f : 0.f;
#pragma unroll
            for (int hh = 0; hh < 8; hh++)
                bias_s[jj * 256 + hh * 32 + ii] = bo[hh] * zf;
        }
        __syncthreads();

        // ---- Phase B: logits + online softmax + AV ----
        float tmax = -INFINITY;
        for (int jj = 0; jj < 32; jj++) {
            const float4* kp =
                (const float4*)(k_s + jj * 512 + h * 64 + half * 32);
            float d0 = 0.f, d1 = 0.f, d2 = 0.f, d3 = 0.f;
#pragma unroll
            for (int t = 0; t < 8; t++) {
                float4 f = kp[t];
                d0 = fmaf(q[4*t+0], f.x, d0);
                d1 = fmaf(q[4*t+1], f.y, d1);
                d2 = fmaf(q[4*t+2], f.z, d2);
                d3 = fmaf(q[4*t+3], f.w, d3);
            }
            float dot = (d0 + d1) + (d2 + d3);
            dot += __shfl_xor_sync(0xffffffffu, dot, 16);
            float lgv = dot + bias_s[jj * 256 + h * 32 + i];
            if (mask_s[jj] > 0.5f) lgv = -1e30f;
            bias_s[jj * 256 + h * 32 + i] = lgv;  // both halves write same value
            tmax = fmaxf(tmax, lgv);
        }
        float mnew = fmaxf(mrun, tmax);
        float corr = __expf(mrun - mnew);
        mrun = mnew;
        l *= corr;
#pragma unroll
        for (int d = 0; d < 32; d++) acc[d] *= corr;

        for (int jj = 0; jj < 32; jj++) {
            float p = __expf(bias_s[jj * 256 + h * 32 + i] - mrun);
            l += p;
            const float4* vp =
                (const float4*)(v_s + jj * 512 + h * 64 + half * 32);
#pragma unroll
            for (int t = 0; t < 8; t++) {
                float4 f = vp[t];
                acc[4*t+0] = fmaf(p, f.x, acc[4*t+0]);
                acc[4*t+1] = fmaf(p, f.y, acc[4*t+1]);
                acc[4*t+2] = fmaf(p, f.z, acc[4*t+2]);
                acc[4*t+3] = fmaf(p, f.w, acc[4*t+3]);
            }
        }
        __syncthreads();
    }

    float invl = 1.f / l;
    float* op = outp + ((size_t)(b * NN + i0 + i)) * 512 + h * 64 + half * 32;
#pragma unroll
    for (int t = 0; t < 8; t++) {
        float4 f;
        f.x = acc[4*t+0] * invl; f.y = acc[4*t+1] * invl;
        f.z = acc[4*t+2] * invl; f.w = acc[4*t+3] * invl;
        ((float4*)op)[t] = f;
    }
}

// ---------------------------------------------------------------------------
extern "C" void kernel_launch(void* const* d_in, const int* in_sizes, int n_in,
                              void* d_out, int out_size)
{
    const float* x      = (const float*)d_in[0];
    const float* coords = (const float*)d_in[1];
    const unsigned char* kpm = (const unsigned char*)d_in[2];
    const float* qkv_w  = (const float*)d_in[3];
    const float* out_w  = (const float*)d_in[4];
    const float* out_b  = (const float*)d_in[5];
    const float* alpha  = (const float*)d_in[6];
    const float* w1     = (const float*)d_in[7];
    const float* b1     = (const float*)d_in[8];
    const float* w2     = (const float*)d_in[9];
    const float* b2     = (const float*)d_in[10];
    const float* cs     = (const float*)d_in[11];
    float* out = (float*)d_out;

    float* qkvp = nullptr;
    float* attnp = nullptr;
    cudaGetSymbolAddress((void**)&qkvp, g_qkv);
    cudaGetSymbolAddress((void**)&attnp, g_attn);

    const int SMEM = 41672 * 4;  // ~163 KB
    cudaFuncSetAttribute(attn_bias_kernel,
                         cudaFuncAttributeMaxDynamicSharedMemorySize, SMEM);

    // 1) QKV projection: [8192,512] @ [512,1536]  (tensor core, tf32 split)
    dim3 g1(1536 / 128, 8192 / 128);
    gemm_tc<<<g1, 256>>>(x, qkv_w, nullptr, qkvp, BB * NN, 3 * DM, DM);

    // 2) Fused bias + attention
    attn_bias_kernel<<<BB * (NN / 32), 512, SMEM>>>(
        qkvp, coords, kpm, w1, b1, w2, b2, cs, alpha, attnp);

    // 3) Output projection: [8192,512] @ [512,512] + bias
    dim3 g3(512 / 128, 8192 / 128);
    gemm_tc<<<g3, 256>>>(attnp, out_w, out_b, out, BB * NN, DM, DM);
}

// round 6
// speedup vs baseline: 2.3142x; 1.1922x over previous
#include <cuda_runtime.h>
#include <math.h>

#define BB 8
#define NN 1024
#define DM 512
#define NH 8
#define HD 64
#define NS_TOK 1

typedef unsigned int uint;

// Scratch (device globals: no allocations allowed in kernel_launch)
__device__ float g_qkv[(size_t)BB * NN * 3 * DM];   // [b][n][1536] : q|k|v
__device__ float g_attn[(size_t)BB * NN * DM];      // [b][n][512]

// ---------------------------------------------------------------------------
// tf32 split helpers (validated by gemm_tc round 4, rel_err 1.4e-5)
// ---------------------------------------------------------------------------
__device__ __forceinline__ unsigned cvt_tf32(float x) {
    unsigned r;
    asm("cvt.rna.tf32.f32 %0, %1;" : "=r"(r) : "f"(x));
    return r;
}
__device__ __forceinline__ void split_tf32(float x, unsigned& hi, unsigned& lo) {
    hi = cvt_tf32(x);
    float rem = x - __uint_as_float(hi);
    lo = cvt_tf32(rem);
}
__device__ __forceinline__ void mma_tf32(
    float& c0, float& c1, float& c2, float& c3,
    unsigned a0, unsigned a1, unsigned a2, unsigned a3,
    unsigned b0, unsigned b1)
{
    asm("mma.sync.aligned.m16n8k8.row.col.f32.tf32.tf32.f32 "
        "{%0,%1,%2,%3}, {%4,%5,%6,%7}, {%8,%9}, {%0,%1,%2,%3};"
        : "+f"(c0), "+f"(c1), "+f"(c2), "+f"(c3)
        : "r"(a0), "r"(a1), "r"(a2), "r"(a3), "r"(b0), "r"(b1));
}

__device__ __forceinline__ float rcp_approx(float x) {
    float r;
    asm("rcp.approx.f32 %0, %1;" : "=f"(r) : "f"(x));
    return r;
}

// Exact-enough gelu (validated rounds 2-4).
__device__ __forceinline__ float gelu_exact(float x) {
    float xs = x * 0.70710678118654752f;
    float ax = fabsf(xs);
    float t = rcp_approx(fmaf(0.3275911f, ax, 1.0f));
    float p = 1.061405429f;
    p = fmaf(p, t, -1.453152027f);
    p = fmaf(p, t, 1.421413741f);
    p = fmaf(p, t, -0.284496736f);
    p = fmaf(p, t, 0.254829592f);
    p = p * t;
    float e = __expf(-ax * ax);
    float er = fmaf(-p, e, 1.0f);
    er = copysignf(er, xs);
    return 0.5f * x * (1.0f + er);
}

// ---------------------------------------------------------------------------
// Tensor-core GEMM (round-4, measured 253us, rel_err 1.4e-5). Unchanged.
// ---------------------------------------------------------------------------
#define ROWPAD 20

__global__ __launch_bounds__(256) void gemm_tc(
    const float* __restrict__ A, const float* __restrict__ W,
    const float* __restrict__ bias, float* __restrict__ C,
    int M, int Nc, int K)
{
    __shared__ float As[128 * ROWPAD];
    __shared__ float Ws[128 * ROWPAD];
    const int tid  = threadIdx.x;
    const int wid  = tid >> 5, lane = tid & 31;
    const int g    = lane >> 2, t4 = lane & 3;
    const int wm   = wid & 1,  wn  = wid >> 1;
    const int brow = blockIdx.y * 128, bcol = blockIdx.x * 128;
    const int m_base = wm * 64, n_base = wn * 32;

    float c[4][4][4];
#pragma unroll
    for (int mf = 0; mf < 4; mf++)
#pragma unroll
        for (int nf = 0; nf < 4; nf++)
#pragma unroll
            for (int r = 0; r < 4; r++) c[mf][nf][r] = 0.f;

    for (int k0 = 0; k0 < K; k0 += 16) {
#pragma unroll
        for (int t = tid; t < 512; t += 256) {
            int m = t >> 2, kq = (t & 3) * 4;
            float4 f = *(const float4*)(A + (size_t)(brow + m) * K + k0 + kq);
            *(float4*)&As[m * ROWPAD + kq] = f;
        }
#pragma unroll
        for (int t = tid; t < 512; t += 256) {
            int n = t >> 2, kq = (t & 3) * 4;
            float4 f = *(const float4*)(W + (size_t)(bcol + n) * K + k0 + kq);
            *(float4*)&Ws[n * ROWPAD + kq] = f;
        }
        __syncthreads();

#pragma unroll
        for (int ks = 0; ks < 16; ks += 8) {
            unsigned ah[4][4], al[4][4];
#pragma unroll
            for (int mf = 0; mf < 4; mf++) {
                int r0 = (m_base + mf * 16 + g) * ROWPAD;
                int r1 = r0 + 8 * ROWPAD;
                split_tf32(As[r0 + ks + t4],     ah[mf][0], al[mf][0]);
                split_tf32(As[r1 + ks + t4],     ah[mf][1], al[mf][1]);
                split_tf32(As[r0 + ks + t4 + 4], ah[mf][2], al[mf][2]);
                split_tf32(As[r1 + ks + t4 + 4], ah[mf][3], al[mf][3]);
            }
            unsigned bh[4][2], bl[4][2];
#pragma unroll
            for (int nf = 0; nf < 4; nf++) {
                int rn = (n_base + nf * 8 + g) * ROWPAD;
                split_tf32(Ws[rn + ks + t4],     bh[nf][0], bl[nf][0]);
                split_tf32(Ws[rn + ks + t4 + 4], bh[nf][1], bl[nf][1]);
            }
#pragma unroll
            for (int mf = 0; mf < 4; mf++)
#pragma unroll
                for (int nf = 0; nf < 4; nf++) {
                    float* cc = c[mf][nf];
                    mma_tf32(cc[0], cc[1], cc[2], cc[3],
                             ah[mf][0], ah[mf][1], ah[mf][2], ah[mf][3],
                             bh[nf][0], bh[nf][1]);
                    mma_tf32(cc[0], cc[1], cc[2], cc[3],
                             ah[mf][0], ah[mf][1], ah[mf][2], ah[mf][3],
                             bl[nf][0], bl[nf][1]);
                    mma_tf32(cc[0], cc[1], cc[2], cc[3],
                             al[mf][0], al[mf][1], al[mf][2], al[mf][3],
                             bh[nf][0], bh[nf][1]);
                }
        }
        __syncthreads();
    }

#pragma unroll
    for (int mf = 0; mf < 4; mf++) {
        int row0 = brow + m_base + mf * 16 + g;
#pragma unroll
        for (int nf = 0; nf < 4; nf++) {
            int col = bcol + n_base + nf * 8 + 2 * t4;
            float b0 = 0.f, b1 = 0.f;
            if (bias) { b0 = bias[col]; b1 = bias[col + 1]; }
            float2 lo, hi;
            lo.x = c[mf][nf][0] + b0; lo.y = c[mf][nf][1] + b1;
            hi.x = c[mf][nf][2] + b0; hi.y = c[mf][nf][3] + b1;
            *(float2*)(C + (size_t)row0 * Nc + col) = lo;
            *(float2*)(C + (size_t)(row0 + 8) * Nc + col) = hi;
        }
    }
}

// ---------------------------------------------------------------------------
// Fused relative-position-bias attention v5: ALL-tf32 tensor-core Phase B
// (only layouts validated by gemm_tc). 512 threads, 16 warps.
// Warp wid: head h = wid>>1, m-half mh = wid&1 (rows mh*16 .. mh*16+15).
// QK^T and AV: tf32 3-MMA split (m16n8k8), per-fragment splits from fp32 smem.
// Softmax: 2 threads per (h, i) row over smem logits; p fp32 in smem.
// Smem floats (53192 total = 212768 B):
//   k_s [32][524] @0, v_s @16768, bias_s[8][32][36] @33536, lg_s @42752,
//   corr_s @51968, l_s @52224, ci @52480, cj @52608, w1 @52736, b1 @52864,
//   w2 @52896, b2 @53152, mask @53160
// ---------------------------------------------------------------------------
__global__ __launch_bounds__(512, 1) void attn_bias_kernel(
    const float* __restrict__ qkv, const float* __restrict__ coords,
    const unsigned char* __restrict__ kpm,
    const float* __restrict__ w1, const float* __restrict__ b1,
    const float* __restrict__ w2, const float* __restrict__ b2,
    const float* __restrict__ cscales, const float* __restrict__ alphap,
    float* __restrict__ outp)
{
    extern __shared__ float sm[];
    float* k_s    = sm;            // [j][524]
    float* v_s    = sm + 16768;    // [j][524]
    float* bias_s = sm + 33536;    // [h][i][36]
    float* lg_s   = sm + 42752;    // [h][i][36]
    float* corr_s = sm + 51968;    // 256
    float* l_s    = sm + 52224;    // 256
    float* ci_s   = sm + 52480;    // 32*4
    float* cj_s   = sm + 52608;    // 32*4
    float* w1_s   = sm + 52736;    // 128
    float* b1_s   = sm + 52864;    // 32
    float* w2_s   = sm + 52896;    // 256 (alpha folded)
    float* b2_s   = sm + 53152;    // 8  (alpha folded)
    float* mask_s = sm + 53160;    // 32

    const int tid  = threadIdx.x;
    const int lane = tid & 31;
    const int wid  = tid >> 5;
    const int h    = wid >> 1;
    const int mh   = wid & 1;
    const int g    = lane >> 2;
    const int t4   = lane & 3;
    const int b    = blockIdx.x >> 5;
    const int i0   = (blockIdx.x & 31) * 32;
    const float alpha = alphap[0];

    // softmax role: 2 threads per (head*32+row)
    const int sr    = tid >> 1;          // 0..255
    const int sjh   = (tid & 1) * 16;
    const int sbase = sr * 36;

    if (tid < 128) w1_s[tid] = w1[tid];
    if (tid < 32)  b1_s[tid] = b1[tid];
    if (tid < 256) w2_s[tid] = alpha * w2[tid];
    if (tid < 8)   b2_s[tid] = alpha * b2[tid];
    if (tid < 32) {
        int ig = i0 + tid;
        ci_s[tid * 4 + 0] = coords[((size_t)b * NN + ig) * 3 + 0] / cscales[0];
        ci_s[tid * 4 + 1] = coords[((size_t)b * NN + ig) * 3 + 1] / cscales[1];
        ci_s[tid * 4 + 2] = coords[((size_t)b * NN + ig) * 3 + 2] / cscales[2];
        ci_s[tid * 4 + 3] = 0.f;
    }

    // Q elements this thread feeds into A-fragments (scale 1/8 folded):
    // qa[ks] = { Q[g][ks*8+t4], Q[g+8][ks*8+t4], Q[g][ks*8+t4+4], Q[g+8][ks*8+t4+4] }
    float qa[8][4];
    {
        const float* q0 = qkv + ((size_t)(b * NN + i0 + mh * 16 + g)) * 1536 + h * 64;
        const float* q8 = q0 + 8 * 1536;
#pragma unroll
        for (int ks = 0; ks < 8; ks++) {
            qa[ks][0] = q0[ks * 8 + t4]     * 0.125f;
            qa[ks][1] = q8[ks * 8 + t4]     * 0.125f;
            qa[ks][2] = q0[ks * 8 + t4 + 4] * 0.125f;
            qa[ks][3] = q8[ks * 8 + t4 + 4] * 0.125f;
        }
    }

    float oacc[8][4];
#pragma unroll
    for (int nf = 0; nf < 8; nf++)
#pragma unroll
        for (int r = 0; r < 4; r++) oacc[nf][r] = 0.f;
    float mrun = -INFINITY, lrun = 0.f;

    __syncthreads();

    for (int j0 = 0; j0 < NN; j0 += 32) {
        // ---- stage K/V tile (fp32) ----
#pragma unroll
        for (int t = tid; t < 4096; t += 512) {
            int jj = t >> 7, c4 = (t & 127) * 4;
            const float* src = qkv + ((size_t)(b * NN + j0 + jj)) * 1536;
            *(float4*)(k_s + jj * 524 + c4) = *(const float4*)(src + 512 + c4);
            *(float4*)(v_s + jj * 524 + c4) = *(const float4*)(src + 1024 + c4);
        }
        if (tid < 32) {
            int jg = j0 + tid;
            mask_s[tid] = kpm[(size_t)b * NN + jg] ? 1.f : 0.f;
            cj_s[tid * 4 + 0] = coords[((size_t)b * NN + jg) * 3 + 0] / cscales[0];
            cj_s[tid * 4 + 1] = coords[((size_t)b * NN + jg) * 3 + 1] / cscales[1];
            cj_s[tid * 4 + 2] = coords[((size_t)b * NN + jg) * 3 + 2] / cscales[2];
            cj_s[tid * 4 + 3] = 0.f;
        }
        __syncthreads();

        // ---- QK^T via tf32 split MMA (gemm_tc-validated layout) ----
        {
            float c[4][4];
#pragma unroll
            for (int nf = 0; nf < 4; nf++)
#pragma unroll
                for (int r = 0; r < 4; r++) c[nf][r] = 0.f;
#pragma unroll
            for (int ks = 0; ks < 8; ks++) {
                uint ah[4], al[4];
                split_tf32(qa[ks][0], ah[0], al[0]);
                split_tf32(qa[ks][1], ah[1], al[1]);
                split_tf32(qa[ks][2], ah[2], al[2]);
                split_tf32(qa[ks][3], ah[3], al[3]);
#pragma unroll
                for (int nf = 0; nf < 4; nf++) {
                    const float* kr = k_s + (nf * 8 + g) * 524 + h * 64 + ks * 8;
                    uint bh0, bl0, bh1, bl1;
                    split_tf32(kr[t4],     bh0, bl0);
                    split_tf32(kr[t4 + 4], bh1, bl1);
                    mma_tf32(c[nf][0], c[nf][1], c[nf][2], c[nf][3],
                             ah[0], ah[1], ah[2], ah[3], bh0, bh1);
                    mma_tf32(c[nf][0], c[nf][1], c[nf][2], c[nf][3],
                             ah[0], ah[1], ah[2], ah[3], bl0, bl1);
                    mma_tf32(c[nf][0], c[nf][1], c[nf][2], c[nf][3],
                             al[0], al[1], al[2], al[3], bh0, bh1);
                }
            }
            const int rowL = h * 1152 + (mh * 16 + g) * 36;
#pragma unroll
            for (int nf = 0; nf < 4; nf++) {
                *(float2*)(lg_s + rowL + nf * 8 + 2 * t4) =
                    make_float2(c[nf][0], c[nf][1]);
                *(float2*)(lg_s + rowL + 8 * 36 + nf * 8 + 2 * t4) =
                    make_float2(c[nf][2], c[nf][3]);
            }
        }

        // ---- Phase A: pairwise bias MLP (scalar, unchanged math) ----
#pragma unroll 1
        for (int pp = 0; pp < 2; pp++) {
            int p  = tid + 512 * pp;
            int jj = p >> 5, ii = p & 31;
            float dx = ci_s[ii * 4 + 0] - cj_s[jj * 4 + 0];
            float dy = ci_s[ii * 4 + 1] - cj_s[jj * 4 + 1];
            float dz = ci_s[ii * 4 + 2] - cj_s[jj * 4 + 2];
            float dist = sqrtf(dx * dx + dy * dy + dz * dz);
            float bo[8];
#pragma unroll
            for (int hh = 0; hh < 8; hh++) bo[hh] = b2_s[hh];
#pragma unroll 4
            for (int kk = 0; kk < 32; kk++) {
                float t2 = b1_s[kk];
                t2 = fmaf(w1_s[kk * 4 + 0], dx,   t2);
                t2 = fmaf(w1_s[kk * 4 + 1], dy,   t2);
                t2 = fmaf(w1_s[kk * 4 + 2], dz,   t2);
                t2 = fmaf(w1_s[kk * 4 + 3], dist, t2);
                float gl = gelu_exact(t2);
#pragma unroll
                for (int hh = 0; hh < 8; hh++)
                    bo[hh] = fmaf(gl, w2_s[hh * 32 + kk], bo[hh]);
            }
            float zf = ((i0 + ii) >= NS_TOK && (j0 + jj) >= NS_TOK) ? 1.f : 0.f;
#pragma unroll
            for (int hh = 0; hh < 8; hh++)
                bias_s[hh * 1152 + ii * 36 + jj] = bo[hh] * zf;
        }
        __syncthreads();

        // ---- softmax: 2 threads per row; p in-place into lg_s ----
        {
            float lg[16];
            float tmax = -INFINITY;
#pragma unroll
            for (int c = 0; c < 16; c++) {
                float x = lg_s[sbase + sjh + c] + bias_s[sbase + sjh + c];
                if (mask_s[sjh + c] > 0.5f) x = -1e30f;
                lg[c] = x;
                tmax = fmaxf(tmax, x);
            }
            tmax = fmaxf(tmax, __shfl_xor_sync(0xffffffffu, tmax, 1));
            float mnew = fmaxf(mrun, tmax);
            float corr = __expf(mrun - mnew);
            mrun = mnew;
            lrun *= corr;
            float ps = 0.f;
#pragma unroll
            for (int c = 0; c < 16; c++) {
                float pv = __expf(lg[c] - mrun);
                ps += pv;
                lg_s[sbase + sjh + c] = pv;
            }
            ps += __shfl_xor_sync(0xffffffffu, ps, 1);
            lrun += ps;
            corr_s[sr] = corr;
        }
        __syncthreads();

        // ---- AV via tf32 split MMA ----
        {
            float corr0 = corr_s[h * 32 + mh * 16 + g];
            float corr1 = corr_s[h * 32 + mh * 16 + g + 8];
#pragma unroll
            for (int nf = 0; nf < 8; nf++) {
                oacc[nf][0] *= corr0; oacc[nf][1] *= corr0;
                oacc[nf][2] *= corr1; oacc[nf][3] *= corr1;
            }
            const int prow = h * 1152 + (mh * 16 + g) * 36;
#pragma unroll
            for (int ks = 0; ks < 4; ks++) {
                uint pah[4], pal[4];
                split_tf32(lg_s[prow + ks * 8 + t4],              pah[0], pal[0]);
                split_tf32(lg_s[prow + 8 * 36 + ks * 8 + t4],     pah[1], pal[1]);
                split_tf32(lg_s[prow + ks * 8 + t4 + 4],          pah[2], pal[2]);
                split_tf32(lg_s[prow + 8 * 36 + ks * 8 + t4 + 4], pah[3], pal[3]);
                const float* vb0 = v_s + (ks * 8 + t4) * 524 + h * 64;
                const float* vb1 = v_s + (ks * 8 + t4 + 4) * 524 + h * 64;
#pragma unroll
                for (int nf = 0; nf < 8; nf++) {
                    uint bh0, bl0, bh1, bl1;
                    split_tf32(vb0[nf * 8 + g], bh0, bl0);
                    split_tf32(vb1[nf * 8 + g], bh1, bl1);
                    mma_tf32(oacc[nf][0], oacc[nf][1], oacc[nf][2], oacc[nf][3],
                             pah[0], pah[1], pah[2], pah[3], bh0, bh1);
                    mma_tf32(oacc[nf][0], oacc[nf][1], oacc[nf][2], oacc[nf][3],
                             pah[0], pah[1], pah[2], pah[3], bl0, bl1);
                    mma_tf32(oacc[nf][0], oacc[nf][1], oacc[nf][2], oacc[nf][3],
                             pal[0], pal[1], pal[2], pal[3], bh0, bh1);
                }
            }
        }
        __syncthreads();
    }

    if ((tid & 1) == 0) l_s[sr] = lrun;
    __syncthreads();

    {
        float inv0 = 1.f / l_s[h * 32 + mh * 16 + g];
        float inv1 = 1.f / l_s[h * 32 + mh * 16 + g + 8];
        float* o0 = outp + ((size_t)(b * NN + i0 + mh * 16 + g)) * 512 + h * 64;
        float* o1 = o0 + 8 * 512;
#pragma unroll
        for (int nf = 0; nf < 8; nf++) {
            *(float2*)(o0 + nf * 8 + 2 * t4) =
                make_float2(oacc[nf][0] * inv0, oacc[nf][1] * inv0);
            *(float2*)(o1 + nf * 8 + 2 * t4) =
                make_float2(oacc[nf][2] * inv1, oacc[nf][3] * inv1);
        }
    }
}

// ---------------------------------------------------------------------------
extern "C" void kernel_launch(void* const* d_in, const int* in_sizes, int n_in,
                              void* d_out, int out_size)
{
    const float* x      = (const float*)d_in[0];
    const float* coords = (const float*)d_in[1];
    const unsigned char* kpm = (const unsigned char*)d_in[2];
    const float* qkv_w  = (const float*)d_in[3];
    const float* out_w  = (const float*)d_in[4];
    const float* out_b  = (const float*)d_in[5];
    const float* alpha  = (const float*)d_in[6];
    const float* w1     = (const float*)d_in[7];
    const float* b1     = (const float*)d_in[8];
    const float* w2     = (const float*)d_in[9];
    const float* b2     = (const float*)d_in[10];
    const float* cs     = (const float*)d_in[11];
    float* out = (float*)d_out;

    float* qkvp = nullptr;
    float* attnp = nullptr;
    cudaGetSymbolAddress((void**)&qkvp, g_qkv);
    cudaGetSymbolAddress((void**)&attnp, g_attn);

    const int SMEM = 53192 * 4;  // 212768 B
    cudaFuncSetAttribute(attn_bias_kernel,
                         cudaFuncAttributeMaxDynamicSharedMemorySize, SMEM);

    // 1) QKV projection: [8192,512] @ [512,1536]  (tensor core, tf32 split)
    dim3 g1(1536 / 128, 8192 / 128);
    gemm_tc<<<g1, 256>>>(x, qkv_w, nullptr, qkvp, BB * NN, 3 * DM, DM);

    // 2) Fused bias + attention (all-tf32 tensor-core Phase B)
    attn_bias_kernel<<<BB * (NN / 32), 512, SMEM>>>(
        qkvp, coords, kpm, w1, b1, w2, b2, cs, alpha, attnp);

    // 3) Output projection: [8192,512] @ [512,512] + bias
    dim3 g3(512 / 128, 8192 / 128);
    gemm_tc<<<g3, 256>>>(attnp, out_w, out_b, out, BB * NN, DM, DM);
}